// round 10
// baseline (speedup 1.0000x reference)
#include <cuda_runtime.h>
#include <cstdint>

#define NB   2
#define NPTS 8192
#define CIN  128
#define COUT 128
#define KNN  21
#define FULLM 0xffffffffu
#define SENT 0xFFFFFFFFFFFFFFFFull
#define FINF __int_as_float(0x7f800000)

// packed f32x2 ops (sm_103a)
#define FMA2(d, a, b, c) asm("fma.rn.f32x2 %0, %1, %2, %3;" : "=l"(d) : "l"(a), "l"(b), "l"(c))
#define MUL2(d, a, b)    asm("mul.rn.f32x2 %0, %1, %2;"     : "=l"(d) : "l"(a), "l"(b))
#define ADD2(d, a, b)    asm("add.rn.f32x2 %0, %1, %2;"     : "=l"(d) : "l"(a), "l"(b))
#define PACK2(d, lo, hi) asm("mov.b64 %0, {%1, %2};" : "=l"(d) : "f"(lo), "f"(hi))
#define UNPK2(lo, hi, s) asm("mov.b64 {%0, %1}, %2;" : "=f"(lo), "=f"(hi) : "l"(s))

// ---------------- scratch (device globals; no allocation allowed) -------------
__device__ __align__(16) float g_Ageo [NB * NPTS * 128];
__device__ __align__(16) float g_Btgeo[NB * NPTS * 128];
__device__ __align__(16) float g_Afeat[NB * NPTS * 128];
__device__ __align__(16) float g_Btfeat[NB * NPTS * 128];
__device__ int   g_idx[NB * NPTS * KNN];
__device__ __align__(16) float g_scale[256];
__device__ __align__(16) float g_shift[256];

// ------------- fused precompute: constants + geo + feat GEMM (f32x2) ---------
// 16-point tile, 256 threads: thread = (o = tid&127, nh = tid>>7).
// acc2[n] = packed (accA_n, accB_n); weights packed (w1-w2, w2); f staged as
// duplicated (f,f) pairs so fma.rn.f32x2 does both GEMMs in one instruction.
__global__ void __launch_bounds__(256) precompute_kernel(
        const float* __restrict__ xyz, const float* __restrict__ f,
        const float* __restrict__ W_geo, const float* __restrict__ W_feat,
        const float* __restrict__ gg, const float* __restrict__ bg,
        const float* __restrict__ mg, const float* __restrict__ vg,
        const float* __restrict__ gf, const float* __restrict__ bf,
        const float* __restrict__ mf, const float* __restrict__ vf) {
    __shared__ __align__(16) unsigned long long sf2[128][16];   // (f,f) pairs
    __shared__ float sxyz[16][3];
    int b  = blockIdx.y;
    int n0 = blockIdx.x * 16;
    int o  = threadIdx.x & 127;
    int nh = threadIdx.x >> 7;          // 0/1: points [nh*8, nh*8+8)

    // BN constants (one block only; 256 threads cover 256 channels)
    if (blockIdx.x == 0 && blockIdx.y == 0) {
        int c = threadIdx.x;
        if (c < 128) {
            float inv = gg[c] * rsqrtf(vg[c] + 1e-5f);
            g_scale[c] = inv;
            g_shift[c] = bg[c] - mg[c] * inv;
        } else {
            int oc = c - 128;
            float inv = gf[oc] * rsqrtf(vf[oc] + 1e-5f);
            g_scale[c] = inv;
            g_shift[c] = bf[oc] - mf[oc] * inv;
        }
    }

    // stage f duplicated: sf2[c][n] = (f, f)
    for (int t = threadIdx.x; t < 128 * 16; t += 256) {
        int c = t >> 4, n = t & 15;
        float v = f[((size_t)b * 128 + c) * NPTS + n0 + n];
        unsigned long long p; PACK2(p, v, v);
        sf2[c][n] = p;
    }
    if (threadIdx.x < 48) {
        int n = threadIdx.x / 3, d = threadIdx.x % 3;
        sxyz[n][d] = xyz[((size_t)b * NPTS + n0 + n) * 3 + d];
    }
    __syncthreads();

    // geo: Ageo = (W03-W36).p ; Btgeo = W36.p   (8 points per thread)
    {
        float w0 = W_geo[o * 6 + 0], w1 = W_geo[o * 6 + 1], w2 = W_geo[o * 6 + 2];
        float w3 = W_geo[o * 6 + 3], w4 = W_geo[o * 6 + 4], w5 = W_geo[o * 6 + 5];
        float wa = w0 - w3, wb = w1 - w4, wc = w2 - w5;
#pragma unroll
        for (int t = 0; t < 8; ++t) {
            int n = nh * 8 + t;
            float x = sxyz[n][0], y = sxyz[n][1], z = sxyz[n][2];
            size_t base = ((size_t)b * NPTS + n0 + n) * 128 + o;
            g_Ageo [base] = fmaf(wa, x, fmaf(wb, y, wc * z));
            g_Btgeo[base] = fmaf(w3, x, fmaf(w4, y, w5 * z));
        }
    }

    // feat GEMM, packed: acc2 = (A, B); one FMA2 per point per channel
    unsigned long long acc2[8];
#pragma unroll
    for (int n = 0; n < 8; ++n) acc2[n] = 0ull;   // (+0.f, +0.f)

    const float4* Wrow = (const float4*)(W_feat + (size_t)o * 256);
#pragma unroll 2
    for (int c4 = 0; c4 < 32; ++c4) {
        float4 w1v = __ldg(&Wrow[c4]);
        float4 w2v = __ldg(&Wrow[32 + c4]);
        float w1s[4] = {w1v.x, w1v.y, w1v.z, w1v.w};
        float w2s[4] = {w2v.x, w2v.y, w2v.z, w2v.w};
#pragma unroll
        for (int cc = 0; cc < 4; ++cc) {
            float w2 = w2s[cc];
            unsigned long long wpk; PACK2(wpk, w1s[cc] - w2, w2);
            const ulonglong2* row = (const ulonglong2*)&sf2[c4 * 4 + cc][nh * 8];
#pragma unroll
            for (int n2 = 0; n2 < 4; ++n2) {
                ulonglong2 v = row[n2];
                FMA2(acc2[n2 * 2 + 0], wpk, v.x, acc2[n2 * 2 + 0]);
                FMA2(acc2[n2 * 2 + 1], wpk, v.y, acc2[n2 * 2 + 1]);
            }
        }
    }
#pragma unroll
    for (int n = 0; n < 8; ++n) {
        float a, bb; UNPK2(a, bb, acc2[n]);
        size_t base = ((size_t)b * NPTS + n0 + nh * 8 + n) * 128 + o;
        g_Afeat [base] = a;
        g_Btfeat[base] = bb;
    }
}

// ---------------- KNN: two-pass, 2 queries/warp ------------------------------
// Pass 1 (packed f32x2): lane processes candidate PAIRS; keeps per-lane min.
// tau = 21st smallest of the 32 lane-minima: they are 32 distinct candidates'
// distances, and the 21st smallest of any subset >= global d21 => valid gate.
// Pass 2 (scalar, unchanged): collect all dist <= tau in index order, then
// exact top-21 by packed (flipped-dist, idx) key == lax.top_k semantics.
#define KNN_CHUNK 1024
#define QCAP 96

__global__ void __launch_bounds__(256) knn_kernel(const float* __restrict__ xyz) {
    // union: pass1 pair-SoA (scA 8KB + scB 8KB) / pass2 float4 AoS (16KB)
    __shared__ __align__(16) unsigned char smbuf[16384];
    __shared__ unsigned long long sQ[16][QCAP];

    int b    = blockIdx.y;
    int warp = threadIdx.x >> 5;
    int lane = threadIdx.x & 31;
    int q0   = blockIdx.x * 16 + warp * 2;
    int q1   = q0 + 1;

    const float* base = xyz + (size_t)b * NPTS * 3;
    float qx0 = base[q0 * 3 + 0], qy0 = base[q0 * 3 + 1], qz0 = base[q0 * 3 + 2];
    float qx1 = base[q1 * 3 + 0], qy1 = base[q1 * 3 + 1], qz1 = base[q1 * 3 + 2];
    float qd0 = fmaf(qx0, qx0, fmaf(qy0, qy0, qz0 * qz0));
    float qd1 = fmaf(qx1, qx1, fmaf(qy1, qy1, qz1 * qz1));

    // packed (dup) query constants
    unsigned long long qx2_0, qy2_0, qz2_0, qd2_0;
    unsigned long long qx2_1, qy2_1, qz2_1, qd2_1, neg2;
    PACK2(qx2_0, qx0, qx0); PACK2(qy2_0, qy0, qy0);
    PACK2(qz2_0, qz0, qz0); PACK2(qd2_0, qd0, qd0);
    PACK2(qx2_1, qx1, qx1); PACK2(qy2_1, qy1, qy1);
    PACK2(qz2_1, qz1, qz1); PACK2(qd2_1, qd1, qd1);
    PACK2(neg2, -2.0f, -2.0f);

    float m0 = FINF, m1 = FINF;   // per-lane minimum distance per query

    // -------- pass 1: packed pairs --------
    float* sA = (float*)smbuf;            // pair i2: (x_e, x_o, y_e, y_o)
    float* sB = (float*)(smbuf + 8192);   // pair i2: (z_e, z_o, w_e, w_o)
    for (int cb = 0; cb < NPTS; cb += KNN_CHUNK) {
        __syncthreads();
        for (int i = threadIdx.x; i < KNN_CHUNK; i += 256) {
            int j = cb + i;
            float x = base[j * 3 + 0];
            float y = base[j * 3 + 1];
            float z = base[j * 3 + 2];
            float d2 = fmaf(x, x, fmaf(y, y, z * z));
            int i2 = i >> 1, h = i & 1;
            sA[i2 * 4 + h]     = x;
            sA[i2 * 4 + 2 + h] = y;
            sB[i2 * 4 + h]     = z;
            sB[i2 * 4 + 2 + h] = d2;
        }
        __syncthreads();

        const ulonglong2* A2 = (const ulonglong2*)sA;
        const ulonglong2* B2 = (const ulonglong2*)sB;
#pragma unroll 2
        for (int i2 = lane; i2 < KNN_CHUNK / 2; i2 += 32) {
            ulonglong2 a = A2[i2];   // .x = x-pair, .y = y-pair
            ulonglong2 c = B2[i2];   // .x = z-pair, .y = w-pair
            unsigned long long t, dot2, s, dist2;
            float lo, hi;
            // query 0 (exact reference formula per half)
            MUL2(t, qz2_0, c.x);
            FMA2(t, qy2_0, a.y, t);
            FMA2(dot2, qx2_0, a.x, t);
            ADD2(s, qd2_0, c.y);
            FMA2(dist2, neg2, dot2, s);
            UNPK2(lo, hi, dist2);
            m0 = fminf(m0, lo); m0 = fminf(m0, hi);
            // query 1
            MUL2(t, qz2_1, c.x);
            FMA2(t, qy2_1, a.y, t);
            FMA2(dot2, qx2_1, a.x, t);
            ADD2(s, qd2_1, c.y);
            FMA2(dist2, neg2, dot2, s);
            UNPK2(lo, hi, dist2);
            m1 = fminf(m1, lo); m1 = fminf(m1, hi);
        }
    }

    // tau = 21st smallest of the 32 lane minima (consume-one per round)
    float tau0, tau1;
    {
        float u = m0, mv;
#pragma unroll 1
        for (int r = 0; r < KNN; ++r) {
            mv = u;
#pragma unroll
            for (int off = 16; off; off >>= 1)
                mv = fminf(mv, __shfl_xor_sync(FULLM, mv, off));
            unsigned msk = __ballot_sync(FULLM, u == mv);
            if (lane == __ffs(msk) - 1) u = FINF;
        }
        tau0 = mv;
        u = m1;
#pragma unroll 1
        for (int r = 0; r < KNN; ++r) {
            mv = u;
#pragma unroll
            for (int off = 16; off; off >>= 1)
                mv = fminf(mv, __shfl_xor_sync(FULLM, mv, off));
            unsigned msk = __ballot_sync(FULLM, u == mv);
            if (lane == __ffs(msk) - 1) u = FINF;
        }
        tau1 = mv;
    }

    // -------- pass 2: scalar collect, all dist <= tau, in index order --------
    unsigned cnt0 = 0, cnt1 = 0;
    unsigned long long* Q0 = sQ[warp * 2 + 0];
    unsigned long long* Q1 = sQ[warp * 2 + 1];
    float4* sc = (float4*)smbuf;

    for (int cb = 0; cb < NPTS; cb += KNN_CHUNK) {
        __syncthreads();
        for (int i = threadIdx.x; i < KNN_CHUNK; i += 256) {
            int j = cb + i;
            float x = base[j * 3 + 0];
            float y = base[j * 3 + 1];
            float z = base[j * 3 + 2];
            float d2 = fmaf(x, x, fmaf(y, y, z * z));
            sc[i] = make_float4(x, y, z, d2);
        }
        __syncthreads();

#pragma unroll 4
        for (int i = lane; i < KNN_CHUNK; i += 32) {
            float4 c = sc[i];
            float dot0  = fmaf(qx0, c.x, fmaf(qy0, c.y, qz0 * c.z));
            float dist0 = fmaf(-2.f, dot0, qd0 + c.w);
            float dot1  = fmaf(qx1, c.x, fmaf(qy1, c.y, qz1 * c.z));
            float dist1 = fmaf(-2.f, dot1, qd1 + c.w);
            bool h0 = (dist0 <= tau0);
            bool h1 = (dist1 <= tau1);
            if (__ballot_sync(FULLM, h0 | h1)) {
                unsigned mk0 = __ballot_sync(FULLM, h0);
                unsigned mk1 = __ballot_sync(FULLM, h1);
                if (h0) {
                    unsigned u = __float_as_uint(dist0);
                    u ^= ((unsigned)((int)u >> 31)) | 0x80000000u;
                    unsigned off = cnt0 + __popc(mk0 & ((1u << lane) - 1u));
                    if (off < QCAP)
                        Q0[off] = ((unsigned long long)u << 32) | (unsigned)(cb + i);
                }
                if (h1) {
                    unsigned u = __float_as_uint(dist1);
                    u ^= ((unsigned)((int)u >> 31)) | 0x80000000u;
                    unsigned off = cnt1 + __popc(mk1 & ((1u << lane) - 1u));
                    if (off < QCAP)
                        Q1[off] = ((unsigned long long)u << 32) | (unsigned)(cb + i);
                }
                cnt0 += __popc(mk0);
                cnt1 += __popc(mk1);
            }
        }
    }
    __syncwarp();

    // -------- final: exact top-21 of each queue by (dist, idx) key --------
#pragma unroll 1
    for (int qi = 0; qi < 2; ++qi) {
        unsigned long long* Q = qi ? Q1 : Q0;
        int n = (int)(qi ? cnt1 : cnt0);
        if (n > QCAP) n = QCAP;
        unsigned long long k0 = (lane      < n) ? Q[lane]      : SENT;
        unsigned long long k1 = (lane + 32 < n) ? Q[lane + 32] : SENT;
        unsigned long long k2 = (lane + 64 < n) ? Q[lane + 64] : SENT;
        int myidx = 0;
#pragma unroll 1
        for (int r = 0; r < KNN; ++r) {
            unsigned long long lo = (k0 < k1) ? k0 : k1;
            unsigned long long best = (lo < k2) ? lo : k2;
            int bsrc = lane;
#pragma unroll
            for (int off = 16; off; off >>= 1) {
                unsigned long long ov = __shfl_xor_sync(FULLM, best, off);
                int os = __shfl_xor_sync(FULLM, bsrc, off);
                if (ov < best || (ov == best && os < bsrc)) { best = ov; bsrc = os; }
            }
            if (lane == r) myidx = (int)(best & 0xffffffffu);
            if (lane == bsrc) {           // keys unique (distinct idx)
                if      (k0 == best) k0 = SENT;
                else if (k1 == best) k1 = SENT;
                else                 k2 = SENT;
            }
        }
        if (lane < KNN)
            g_idx[((size_t)b * NPTS + (qi ? q1 : q0)) * KNN + lane] = myidx;
    }
}

// ---------------- gather-max + epilogue --------------------------------------
__device__ __forceinline__ float4 fmax4(float4 a, float4 b) {
    return make_float4(fmaxf(a.x, b.x), fmaxf(a.y, b.y),
                       fmaxf(a.z, b.z), fmaxf(a.w, b.w));
}

__global__ void __launch_bounds__(256) gather_max_kernel(float* __restrict__ out) {
    __shared__ int   sidx[32][KNN];
    __shared__ float sout[256 * 33];

    int b    = blockIdx.y;
    int n0   = blockIdx.x * 32;
    int warp = threadIdx.x >> 5;
    int lane = threadIdx.x & 31;

    for (int t = threadIdx.x; t < 32 * KNN; t += 256)
        sidx[t / KNN][t % KNN] = g_idx[((size_t)b * NPTS + n0) * KNN + t];
    __syncthreads();

    const float4* BG = (const float4*)g_Btgeo;
    const float4* BF = (const float4*)g_Btfeat;
    const float4* AG = (const float4*)g_Ageo;
    const float4* AF = (const float4*)g_Afeat;
    const float4* S4 = (const float4*)g_scale;
    const float4* H4 = (const float4*)g_shift;

    float4 scg = S4[lane],        shg = H4[lane];
    float4 scf = S4[32 + lane],   shf = H4[32 + lane];

    for (int pi = 0; pi < 4; ++pi) {
        int p = warp * 4 + pi;
        int n = n0 + p;
        float4 mg = make_float4(-3.4e38f, -3.4e38f, -3.4e38f, -3.4e38f);
        float4 mf = mg;
#pragma unroll
        for (int k = 0; k < KNN; ++k) {
            int j = sidx[p][k];
            size_t col = ((size_t)b * NPTS + j) * 32 + lane;
            mg = fmax4(mg, BG[col]);
            mf = fmax4(mf, BF[col]);
        }
        size_t acol = ((size_t)b * NPTS + n) * 32 + lane;
        float4 ag = AG[acol];
        float4 af = AF[acol];

        int cg = lane * 4;
        sout[(cg + 0) * 33 + p] = fmaxf(fmaf(mg.x + ag.x, scg.x, shg.x), 0.f);
        sout[(cg + 1) * 33 + p] = fmaxf(fmaf(mg.y + ag.y, scg.y, shg.y), 0.f);
        sout[(cg + 2) * 33 + p] = fmaxf(fmaf(mg.z + ag.z, scg.z, shg.z), 0.f);
        sout[(cg + 3) * 33 + p] = fmaxf(fmaf(mg.w + ag.w, scg.w, shg.w), 0.f);
        int cf = 128 + lane * 4;
        sout[(cf + 0) * 33 + p] = fmaxf(fmaf(mf.x + af.x, scf.x, shf.x), 0.f);
        sout[(cf + 1) * 33 + p] = fmaxf(fmaf(mf.y + af.y, scf.y, shf.y), 0.f);
        sout[(cf + 2) * 33 + p] = fmaxf(fmaf(mf.z + af.z, scf.z, shf.z), 0.f);
        sout[(cf + 3) * 33 + p] = fmaxf(fmaf(mf.w + af.w, scf.w, shf.w), 0.f);
    }
    __syncthreads();

    for (int c = warp; c < 256; c += 8)
        out[((size_t)b * 256 + c) * NPTS + n0 + lane] = sout[c * 33 + lane];
}

// ---------------- launch ------------------------------------------------------
extern "C" void kernel_launch(void* const* d_in, const int* in_sizes, int n_in,
                              void* d_out, int out_size) {
    const float* xyz    = (const float*)d_in[0];
    const float* f      = (const float*)d_in[1];
    const float* W_geo  = (const float*)d_in[2];
    const float* g_geo  = (const float*)d_in[3];
    const float* b_geo  = (const float*)d_in[4];
    const float* m_geo  = (const float*)d_in[5];
    const float* v_geo  = (const float*)d_in[6];
    const float* W_feat = (const float*)d_in[7];
    const float* g_feat = (const float*)d_in[8];
    const float* b_feat = (const float*)d_in[9];
    const float* m_feat = (const float*)d_in[10];
    const float* v_feat = (const float*)d_in[11];
    float* out = (float*)d_out;

    precompute_kernel<<<dim3(NPTS / 16, NB), 256>>>(
        xyz, f, W_geo, W_feat,
        g_geo, b_geo, m_geo, v_geo, g_feat, b_feat, m_feat, v_feat);
    knn_kernel<<<dim3(NPTS / 16, NB), 256>>>(xyz);
    gather_max_kernel<<<dim3(NPTS / 32, NB), 256>>>(out);
}

// round 12
// speedup vs baseline: 1.3007x; 1.3007x over previous
#include <cuda_runtime.h>
#include <cstdint>

#define NB   2
#define NPTS 8192
#define CIN  128
#define COUT 128
#define KNN  21
#define FULLM 0xffffffffu
#define SENT 0xFFFFFFFFFFFFFFFFull
#define FINF __int_as_float(0x7f800000)

// packed f32x2 ops (sm_103a)
#define FMA2(d, a, b, c) asm("fma.rn.f32x2 %0, %1, %2, %3;" : "=l"(d) : "l"(a), "l"(b), "l"(c))
#define PACK2(d, lo, hi) asm("mov.b64 %0, {%1, %2};" : "=l"(d) : "f"(lo), "f"(hi))
#define UNPK2(lo, hi, s) asm("mov.b64 {%0, %1}, %2;" : "=f"(lo), "=f"(hi) : "l"(s))

// ---------------- scratch (device globals; no allocation allowed) -------------
__device__ __align__(16) float g_Ageo [NB * NPTS * 128];
__device__ __align__(16) float g_Btgeo[NB * NPTS * 128];
__device__ __align__(16) float g_Afeat[NB * NPTS * 128];
__device__ __align__(16) float g_Btfeat[NB * NPTS * 128];
__device__ int   g_idx[NB * NPTS * KNN];
__device__ __align__(16) float g_scale[256];
__device__ __align__(16) float g_shift[256];
__device__ __align__(16) float2 g_wp[128 * 128];   // [c][o] = (w1-w2, w2)

// ------------- prep: BN constants + weight transpose -------------------------
__global__ void __launch_bounds__(256) prep_kernel(
        const float* __restrict__ W_feat,
        const float* __restrict__ gg, const float* __restrict__ bg,
        const float* __restrict__ mg, const float* __restrict__ vg,
        const float* __restrict__ gf, const float* __restrict__ bf,
        const float* __restrict__ mf, const float* __restrict__ vf) {
    int idx = blockIdx.x * 256 + threadIdx.x;      // 64 blocks -> 16384
    int o = idx >> 7;          // coalesced read along c
    int c = idx & 127;
    float w1 = W_feat[o * 256 + c];
    float w2 = W_feat[o * 256 + 128 + c];
    g_wp[c * 128 + o] = make_float2(w1 - w2, w2);

    if (blockIdx.x == 0) {
        int t = threadIdx.x;
        if (t < 128) {
            float inv = gg[t] * rsqrtf(vg[t] + 1e-5f);
            g_scale[t] = inv;
            g_shift[t] = bg[t] - mg[t] * inv;
        } else {
            int oc = t - 128;
            float inv = gf[oc] * rsqrtf(vf[oc] + 1e-5f);
            g_scale[t] = inv;
            g_shift[t] = bf[oc] - mf[oc] * inv;
        }
    }
}

// ------------- fused precompute: geo + feat GEMM (f32x2 point-pairs) ---------
// 32-point tile, 256 threads: thread = (o = tid&127, nh = tid>>7), 16 points.
// accA[k]/accB[k] hold packed point-pairs (val_{2k}, val_{2k+1}); weights are
// dup-packed per channel. One LDS.128 of sf yields two packed f-pair operands.
__global__ void __launch_bounds__(256) precompute_kernel(
        const float* __restrict__ xyz, const float* __restrict__ f,
        const float* __restrict__ W_geo) {
    __shared__ __align__(16) float sf[128][32];
    __shared__ float sxyz[32][3];
    int b  = blockIdx.y;
    int n0 = blockIdx.x * 32;
    int o  = threadIdx.x & 127;
    int nh = threadIdx.x >> 7;          // 0/1: points [nh*16, nh*16+16)

    for (int t = threadIdx.x; t < 128 * 32; t += 256) {
        int c = t >> 5, n = t & 31;
        sf[c][n] = f[((size_t)b * 128 + c) * NPTS + n0 + n];
    }
    if (threadIdx.x < 96) {
        int n = threadIdx.x / 3, d = threadIdx.x % 3;
        sxyz[n][d] = xyz[((size_t)b * NPTS + n0 + n) * 3 + d];
    }
    __syncthreads();

    // geo: Ageo = (W03-W36).p ; Btgeo = W36.p   (16 points per thread)
    {
        float w0 = W_geo[o * 6 + 0], w1 = W_geo[o * 6 + 1], w2 = W_geo[o * 6 + 2];
        float w3 = W_geo[o * 6 + 3], w4 = W_geo[o * 6 + 4], w5 = W_geo[o * 6 + 5];
        float wa = w0 - w3, wb = w1 - w4, wc = w2 - w5;
#pragma unroll 4
        for (int t = 0; t < 16; ++t) {
            int n = nh * 16 + t;
            float x = sxyz[n][0], y = sxyz[n][1], z = sxyz[n][2];
            size_t base = ((size_t)b * NPTS + n0 + n) * 128 + o;
            g_Ageo [base] = fmaf(wa, x, fmaf(wb, y, wc * z));
            g_Btgeo[base] = fmaf(w3, x, fmaf(w4, y, w5 * z));
        }
    }

    // feat GEMM: 8 packed A-pairs + 8 packed B-pairs (16 points)
    unsigned long long accA[8], accB[8];
#pragma unroll
    for (int k = 0; k < 8; ++k) { accA[k] = 0ull; accB[k] = 0ull; }

    const float2* __restrict__ wp = g_wp;
#pragma unroll 4
    for (int c = 0; c < 128; ++c) {
        float2 w = __ldg(&wp[c * 128 + o]);          // coalesced, L1-resident
        unsigned long long wm2, w22;
        PACK2(wm2, w.x, w.x);
        PACK2(w22, w.y, w.y);
        const ulonglong2* row = (const ulonglong2*)&sf[c][nh * 16];
#pragma unroll
        for (int p = 0; p < 4; ++p) {
            ulonglong2 v = row[p];   // pairs (f_{4p}, f_{4p+1}), (f_{4p+2}, f_{4p+3})
            FMA2(accA[p * 2 + 0], wm2, v.x, accA[p * 2 + 0]);
            FMA2(accB[p * 2 + 0], w22, v.x, accB[p * 2 + 0]);
            FMA2(accA[p * 2 + 1], wm2, v.y, accA[p * 2 + 1]);
            FMA2(accB[p * 2 + 1], w22, v.y, accB[p * 2 + 1]);
        }
    }
#pragma unroll
    for (int k = 0; k < 8; ++k) {
        float a0, a1, b0, b1;
        UNPK2(a0, a1, accA[k]);
        UNPK2(b0, b1, accB[k]);
        size_t base = ((size_t)b * NPTS + n0 + nh * 16 + 2 * k) * 128 + o;
        g_Afeat [base]       = a0;
        g_Afeat [base + 128] = a1;
        g_Btfeat[base]       = b0;
        g_Btfeat[base + 128] = b1;
    }
}

// ---------------- KNN: two-pass, 2 queries/warp, per-lane top-1 bound --------
// Pass 1: each lane keeps only its single smallest distance (1 FMNMX/cand).
// tau = 21st smallest of the 32 lane-minima (subset of all candidates =>
// tau >= true d21, valid conservative gate). Expected pass-2 queue ~34.
// Pass 2: collect all dist <= tau (ballot-append, index order), then exact
// top-21 by packed (flipped-dist, idx) key == lax.top_k(-dist) semantics.
#define KNN_CHUNK 1024
#define QCAP 96

__global__ void __launch_bounds__(256) knn_kernel(const float* __restrict__ xyz) {
    __shared__ float4 sc[KNN_CHUNK];
    __shared__ unsigned long long sQ[16][QCAP];

    int b    = blockIdx.y;
    int warp = threadIdx.x >> 5;
    int lane = threadIdx.x & 31;
    int q0   = blockIdx.x * 16 + warp * 2;
    int q1   = q0 + 1;

    const float* base = xyz + (size_t)b * NPTS * 3;
    float qx0 = base[q0 * 3 + 0], qy0 = base[q0 * 3 + 1], qz0 = base[q0 * 3 + 2];
    float qx1 = base[q1 * 3 + 0], qy1 = base[q1 * 3 + 1], qz1 = base[q1 * 3 + 2];
    float qd0 = fmaf(qx0, qx0, fmaf(qy0, qy0, qz0 * qz0));
    float qd1 = fmaf(qx1, qx1, fmaf(qy1, qy1, qz1 * qz1));

    float m0 = FINF, m1 = FINF;   // per-lane minimum distance per query

    // -------- pass 1 --------
    for (int cb = 0; cb < NPTS; cb += KNN_CHUNK) {
        __syncthreads();
        for (int i = threadIdx.x; i < KNN_CHUNK; i += 256) {
            int j = cb + i;
            float x = base[j * 3 + 0];
            float y = base[j * 3 + 1];
            float z = base[j * 3 + 2];
            float d2 = fmaf(x, x, fmaf(y, y, z * z));
            sc[i] = make_float4(x, y, z, d2);
        }
        __syncthreads();

#pragma unroll 4
        for (int i = lane; i < KNN_CHUNK; i += 32) {
            float4 c = sc[i];
            float dot0  = fmaf(qx0, c.x, fmaf(qy0, c.y, qz0 * c.z));
            float dist0 = fmaf(-2.f, dot0, qd0 + c.w);   // reference formula
            float dot1  = fmaf(qx1, c.x, fmaf(qy1, c.y, qz1 * c.z));
            float dist1 = fmaf(-2.f, dot1, qd1 + c.w);
            m0 = fminf(m0, dist0);
            m1 = fminf(m1, dist1);
        }
    }

    // tau = 21st smallest of the 32 lane minima (consume-one per round)
    float tau0, tau1;
    {
        float u = m0, mv;
#pragma unroll 1
        for (int r = 0; r < KNN; ++r) {
            mv = u;
#pragma unroll
            for (int off = 16; off; off >>= 1)
                mv = fminf(mv, __shfl_xor_sync(FULLM, mv, off));
            unsigned msk = __ballot_sync(FULLM, u == mv);
            if (lane == __ffs(msk) - 1) u = FINF;
        }
        tau0 = mv;
        u = m1;
#pragma unroll 1
        for (int r = 0; r < KNN; ++r) {
            mv = u;
#pragma unroll
            for (int off = 16; off; off >>= 1)
                mv = fminf(mv, __shfl_xor_sync(FULLM, mv, off));
            unsigned msk = __ballot_sync(FULLM, u == mv);
            if (lane == __ffs(msk) - 1) u = FINF;
        }
        tau1 = mv;
    }

    // -------- pass 2: collect all dist <= tau, in index order --------
    unsigned cnt0 = 0, cnt1 = 0;
    unsigned long long* Q0 = sQ[warp * 2 + 0];
    unsigned long long* Q1 = sQ[warp * 2 + 1];

    for (int cb = 0; cb < NPTS; cb += KNN_CHUNK) {
        __syncthreads();
        for (int i = threadIdx.x; i < KNN_CHUNK; i += 256) {
            int j = cb + i;
            float x = base[j * 3 + 0];
            float y = base[j * 3 + 1];
            float z = base[j * 3 + 2];
            float d2 = fmaf(x, x, fmaf(y, y, z * z));
            sc[i] = make_float4(x, y, z, d2);
        }
        __syncthreads();

#pragma unroll 4
        for (int i = lane; i < KNN_CHUNK; i += 32) {
            float4 c = sc[i];
            float dot0  = fmaf(qx0, c.x, fmaf(qy0, c.y, qz0 * c.z));
            float dist0 = fmaf(-2.f, dot0, qd0 + c.w);
            float dot1  = fmaf(qx1, c.x, fmaf(qy1, c.y, qz1 * c.z));
            float dist1 = fmaf(-2.f, dot1, qd1 + c.w);
            bool h0 = (dist0 <= tau0);
            bool h1 = (dist1 <= tau1);
            // single combined ballot on the fast path
            if (__ballot_sync(FULLM, h0 | h1)) {
                unsigned mk0 = __ballot_sync(FULLM, h0);
                unsigned mk1 = __ballot_sync(FULLM, h1);
                if (h0) {
                    unsigned u = __float_as_uint(dist0);
                    u ^= ((unsigned)((int)u >> 31)) | 0x80000000u;
                    unsigned off = cnt0 + __popc(mk0 & ((1u << lane) - 1u));
                    if (off < QCAP)
                        Q0[off] = ((unsigned long long)u << 32) | (unsigned)(cb + i);
                }
                if (h1) {
                    unsigned u = __float_as_uint(dist1);
                    u ^= ((unsigned)((int)u >> 31)) | 0x80000000u;
                    unsigned off = cnt1 + __popc(mk1 & ((1u << lane) - 1u));
                    if (off < QCAP)
                        Q1[off] = ((unsigned long long)u << 32) | (unsigned)(cb + i);
                }
                cnt0 += __popc(mk0);
                cnt1 += __popc(mk1);
            }
        }
    }
    __syncwarp();

    // -------- final: exact top-21 of each queue by (dist, idx) key --------
#pragma unroll 1
    for (int qi = 0; qi < 2; ++qi) {
        unsigned long long* Q = qi ? Q1 : Q0;
        int n = (int)(qi ? cnt1 : cnt0);
        if (n > QCAP) n = QCAP;
        unsigned long long k0 = (lane      < n) ? Q[lane]      : SENT;
        unsigned long long k1 = (lane + 32 < n) ? Q[lane + 32] : SENT;
        unsigned long long k2 = (lane + 64 < n) ? Q[lane + 64] : SENT;
        int myidx = 0;
#pragma unroll 1
        for (int r = 0; r < KNN; ++r) {
            unsigned long long lo = (k0 < k1) ? k0 : k1;
            unsigned long long best = (lo < k2) ? lo : k2;
            int bsrc = lane;
#pragma unroll
            for (int off = 16; off; off >>= 1) {
                unsigned long long ov = __shfl_xor_sync(FULLM, best, off);
                int os = __shfl_xor_sync(FULLM, bsrc, off);
                if (ov < best || (ov == best && os < bsrc)) { best = ov; bsrc = os; }
            }
            if (lane == r) myidx = (int)(best & 0xffffffffu);
            if (lane == bsrc) {           // keys unique (distinct idx)
                if      (k0 == best) k0 = SENT;
                else if (k1 == best) k1 = SENT;
                else                 k2 = SENT;
            }
        }
        if (lane < KNN)
            g_idx[((size_t)b * NPTS + (qi ? q1 : q0)) * KNN + lane] = myidx;
    }
}

// ---------------- gather-max + epilogue --------------------------------------
__device__ __forceinline__ float4 fmax4(float4 a, float4 b) {
    return make_float4(fmaxf(a.x, b.x), fmaxf(a.y, b.y),
                       fmaxf(a.z, b.z), fmaxf(a.w, b.w));
}

__global__ void __launch_bounds__(256) gather_max_kernel(float* __restrict__ out) {
    __shared__ int   sidx[32][KNN];
    __shared__ float sout[256 * 33];

    int b    = blockIdx.y;
    int n0   = blockIdx.x * 32;
    int warp = threadIdx.x >> 5;
    int lane = threadIdx.x & 31;

    for (int t = threadIdx.x; t < 32 * KNN; t += 256)
        sidx[t / KNN][t % KNN] = g_idx[((size_t)b * NPTS + n0) * KNN + t];
    __syncthreads();

    const float4* BG = (const float4*)g_Btgeo;
    const float4* BF = (const float4*)g_Btfeat;
    const float4* AG = (const float4*)g_Ageo;
    const float4* AF = (const float4*)g_Afeat;
    const float4* S4 = (const float4*)g_scale;
    const float4* H4 = (const float4*)g_shift;

    float4 scg = S4[lane],        shg = H4[lane];
    float4 scf = S4[32 + lane],   shf = H4[32 + lane];

    for (int pi = 0; pi < 4; ++pi) {
        int p = warp * 4 + pi;
        int n = n0 + p;
        float4 mg = make_float4(-3.4e38f, -3.4e38f, -3.4e38f, -3.4e38f);
        float4 mf = mg;
#pragma unroll
        for (int k = 0; k < KNN; ++k) {
            int j = sidx[p][k];
            size_t col = ((size_t)b * NPTS + j) * 32 + lane;
            mg = fmax4(mg, BG[col]);
            mf = fmax4(mf, BF[col]);
        }
        size_t acol = ((size_t)b * NPTS + n) * 32 + lane;
        float4 ag = AG[acol];
        float4 af = AF[acol];

        int cg = lane * 4;
        sout[(cg + 0) * 33 + p] = fmaxf(fmaf(mg.x + ag.x, scg.x, shg.x), 0.f);
        sout[(cg + 1) * 33 + p] = fmaxf(fmaf(mg.y + ag.y, scg.y, shg.y), 0.f);
        sout[(cg + 2) * 33 + p] = fmaxf(fmaf(mg.z + ag.z, scg.z, shg.z), 0.f);
        sout[(cg + 3) * 33 + p] = fmaxf(fmaf(mg.w + ag.w, scg.w, shg.w), 0.f);
        int cf = 128 + lane * 4;
        sout[(cf + 0) * 33 + p] = fmaxf(fmaf(mf.x + af.x, scf.x, shf.x), 0.f);
        sout[(cf + 1) * 33 + p] = fmaxf(fmaf(mf.y + af.y, scf.y, shf.y), 0.f);
        sout[(cf + 2) * 33 + p] = fmaxf(fmaf(mf.z + af.z, scf.z, shf.z), 0.f);
        sout[(cf + 3) * 33 + p] = fmaxf(fmaf(mf.w + af.w, scf.w, shf.w), 0.f);
    }
    __syncthreads();

    for (int c = warp; c < 256; c += 8)
        out[((size_t)b * 256 + c) * NPTS + n0 + lane] = sout[c * 33 + lane];
}

// ---------------- launch ------------------------------------------------------
extern "C" void kernel_launch(void* const* d_in, const int* in_sizes, int n_in,
                              void* d_out, int out_size) {
    const float* xyz    = (const float*)d_in[0];
    const float* f      = (const float*)d_in[1];
    const float* W_geo  = (const float*)d_in[2];
    const float* g_geo  = (const float*)d_in[3];
    const float* b_geo  = (const float*)d_in[4];
    const float* m_geo  = (const float*)d_in[5];
    const float* v_geo  = (const float*)d_in[6];
    const float* W_feat = (const float*)d_in[7];
    const float* g_feat = (const float*)d_in[8];
    const float* b_feat = (const float*)d_in[9];
    const float* m_feat = (const float*)d_in[10];
    const float* v_feat = (const float*)d_in[11];
    float* out = (float*)d_out;

    prep_kernel<<<64, 256>>>(W_feat,
        g_geo, b_geo, m_geo, v_geo, g_feat, b_feat, m_feat, v_feat);
    precompute_kernel<<<dim3(NPTS / 32, NB), 256>>>(xyz, f, W_geo);
    knn_kernel<<<dim3(NPTS / 16, NB), 256>>>(xyz);
    gather_max_kernel<<<dim3(NPTS / 32, NB), 256>>>(out);
}